// round 16
// baseline (speedup 1.0000x reference)
#include <cuda_runtime.h>
#include <cuda_bf16.h>
#include <cstdint>
#include <math.h>

#define N_IMG   32
#define C_DIM   128
#define K_CL    64
#define S_TOT   12544
#define SC      128
#define NCHUNK  98
#define SPLIT   9
#define CPB     11
#define THREADS 512
#define EPSV    1e-12f

#define XSTR    272         // X tile row stride bytes (256 + 16; 17 odd 16B units)
#define WSTR    272
#define PSTR    272

// smem byte offsets
#define OFF_XH  0
#define OFF_WH  (OFF_XH  + 128 * XSTR)      //  34816
#define OFF_PH  (OFF_WH  +  64 * WSTR)      //  52224
#define OFF_EXC (OFF_PH  +  64 * PSTR)      //  69632  float2[2][128]
#define OFF_ASR (OFF_EXC + 2 * 128 * 8)     //  71680  float[16][32]
#define SMEM_BYTES (OFF_ASR + 16 * 32 * 4)  //  73728

__device__ float g_vpart[(size_t)N_IMG * SPLIT * K_CL * C_DIM];
__device__ float g_apart[N_IMG * SPLIT * K_CL];
__device__ float g_gsum[N_IMG * 8];

// ---------------- PTX helpers ----------------
__device__ __forceinline__ void ldsm4(uint32_t* r, uint32_t a) {
    asm volatile("ldmatrix.sync.aligned.m8n8.x4.shared.b16 {%0,%1,%2,%3}, [%4];"
        : "=r"(r[0]), "=r"(r[1]), "=r"(r[2]), "=r"(r[3]) : "r"(a));
}
__device__ __forceinline__ void ldsm4t(uint32_t* r, uint32_t a) {
    asm volatile("ldmatrix.sync.aligned.m8n8.x4.trans.shared.b16 {%0,%1,%2,%3}, [%4];"
        : "=r"(r[0]), "=r"(r[1]), "=r"(r[2]), "=r"(r[3]) : "r"(a));
}
__device__ __forceinline__ void mma16816(float* d, const uint32_t* a, const uint32_t* b) {
    asm volatile("mma.sync.aligned.m16n8k16.row.col.f32.bf16.bf16.f32 "
        "{%0,%1,%2,%3}, {%4,%5,%6,%7}, {%8,%9}, {%0,%1,%2,%3};"
        : "+f"(d[0]), "+f"(d[1]), "+f"(d[2]), "+f"(d[3])
        : "r"(a[0]), "r"(a[1]), "r"(a[2]), "r"(a[3]), "r"(b[0]), "r"(b[1]));
}
__device__ __forceinline__ uint32_t pack_hi(float a, float b) {
    __nv_bfloat16 ah = __float2bfloat16_rn(a);
    __nv_bfloat16 bh = __float2bfloat16_rn(b);
    return (uint32_t)__bfloat16_as_ushort(ah) | ((uint32_t)__bfloat16_as_ushort(bh) << 16);
}

__global__ void __launch_bounds__(THREADS, 1)
netvlad_main(const float* __restrict__ x, const float* __restrict__ convw) {
    extern __shared__ char smb[];
    const uint32_t sb = (uint32_t)__cvta_generic_to_shared(smb);

    const int n   = blockIdx.y;
    const int sp  = blockIdx.x;
    const int tid = threadIdx.x;
    const int w   = tid >> 5, l = tid & 31;

    const int half = w & 1;               // k half: n0 = half*32
    const int n0   = half * 32;
    const int t0   = (w >> 1) * 16;       // s-tile (GEMM1) / c-tile (GEMM2) base
    const int sr0  = t0 + (l >> 2);       // softmax row 0 (row 1 = sr0+8)

    // fragment address components
    const uint32_t raT  = ((l >> 4) & 1) * 8 + (l & 7);    // trans A rows
    const uint32_t caT  = (t0 + ((l >> 3) & 1) * 8) * 2;   // trans A col bytes
    const uint32_t raN  = ((l >> 3) & 1) * 8 + (l & 7);    // normal A rows
    const uint32_t caN  = ((l >> 4) & 1) * 16;             // normal A col bytes
    const uint32_t rbX  = ((l >> 4) & 1) * 8 + (l & 7);    // B x4 rows
    const uint32_t cb16 = ((l >> 3) & 1) * 16;

    // ---- W -> bf16 hi tile [k][WSTR] ----
    {
        const int k = tid >> 3, cs = (tid & 7) * 16;
        const float* wg = convw + k * C_DIM + cs;
        #pragma unroll
        for (int g = 0; g < 2; g++) {
            uint32_t hh[4];
            #pragma unroll
            for (int j = 0; j < 4; j++)
                hh[j] = pack_hi(wg[8 * g + 2 * j], wg[8 * g + 2 * j + 1]);
            *(uint4*)(smb + OFF_WH + k * WSTR + (cs + 8 * g) * 2) =
                make_uint4(hh[0], hh[1], hh[2], hh[3]);
        }
    }

    const int chunk0 = sp * CPB;
    const int nch    = min(NCHUNK, chunk0 + CPB) - chunk0;
    const int sbase  = chunk0 * SC;
    const float* xb  = x + (size_t)n * C_DIM * S_TOT;

    // X staging: thread owns channel Lc, 32 px at Ls0
    const int Lc = tid >> 2, Ls0 = (tid & 3) * 32;

    float vacc[4][4];
    #pragma unroll
    for (int t = 0; t < 4; t++)
        #pragma unroll
        for (int i = 0; i < 4; i++) vacc[t][i] = 0.f;
    float asum_loc[8];
    #pragma unroll
    for (int i = 0; i < 8; i++) asum_loc[i] = 0.f;

    float4 ld[8];
    {
        const float* g = xb + (size_t)Lc * S_TOT + sbase + Ls0;
        #pragma unroll
        for (int r = 0; r < 8; r++) ld[r] = *(const float4*)(g + 4 * r);
    }
    __syncthreads();   // W ready

    for (int ci = 0; ci < nch; ci++) {
        // ---- phase 1: convert + store X hi [c][s] ----
        const uint32_t xo = Lc * XSTR + Ls0 * 2;
        #pragma unroll
        for (int g4 = 0; g4 < 4; g4++) {
            float f[8] = { ld[2*g4].x, ld[2*g4].y, ld[2*g4].z, ld[2*g4].w,
                           ld[2*g4+1].x, ld[2*g4+1].y, ld[2*g4+1].z, ld[2*g4+1].w };
            uint32_t hh[4];
            #pragma unroll
            for (int j = 0; j < 4; j++)
                hh[j] = pack_hi(f[2*j], f[2*j+1]);
            *(uint4*)(smb + OFF_XH + xo + 16 * g4) =
                make_uint4(hh[0], hh[1], hh[2], hh[3]);
        }
        __syncthreads();

        // ---- phase 2: GEMM1  D1[s][k] = X^T W^T  (full chunk, 16 warps) ----
        float d1[4][4];
        #pragma unroll
        for (int t = 0; t < 4; t++)
            #pragma unroll
            for (int i = 0; i < 4; i++) d1[t][i] = 0.f;

        #pragma unroll
        for (int kq = 0; kq < 8; kq++) {
            uint32_t Ah[4];
            ldsm4t(Ah, sb + OFF_XH + (kq * 16 + raT) * XSTR + caT);
            #pragma unroll
            for (int ntp = 0; ntp < 2; ntp++) {
                uint32_t Bh[4];
                ldsm4(Bh, sb + OFF_WH + (n0 + ntp * 16 + rbX) * WSTR + kq * 32 + cb16);
                mma16816(d1[2*ntp],   Ah, Bh);
                mma16816(d1[2*ntp+1], Ah, Bh + 2);
            }
        }

        // prefetch next chunk's X (hidden under softmax + GEMM2)
        if (ci + 1 < nch) {
            const float* g = xb + (size_t)Lc * S_TOT + sbase + (ci + 1) * SC + Ls0;
            #pragma unroll
            for (int r = 0; r < 8; r++) ld[r] = *(const float4*)(g + 4 * r);
        }

        // ---- phase 3: softmax in registers ----
        // d1[nt][i]: row = sr0 + (i>>1)*8, k = n0 + nt*8 + (l&3)*2 + (i&1)
        float m0 = d1[0][0], m1 = d1[0][2];
        #pragma unroll
        for (int nt = 0; nt < 4; nt++) {
            m0 = fmaxf(m0, fmaxf(d1[nt][0], d1[nt][1]));
            m1 = fmaxf(m1, fmaxf(d1[nt][2], d1[nt][3]));
        }
        m0 = fmaxf(m0, __shfl_xor_sync(0xffffffffu, m0, 1));
        m0 = fmaxf(m0, __shfl_xor_sync(0xffffffffu, m0, 2));
        m1 = fmaxf(m1, __shfl_xor_sync(0xffffffffu, m1, 1));
        m1 = fmaxf(m1, __shfl_xor_sync(0xffffffffu, m1, 2));
        float s0e = 0.f, s1e = 0.f;
        #pragma unroll
        for (int nt = 0; nt < 4; nt++) {
            d1[nt][0] = __expf(d1[nt][0] - m0); s0e += d1[nt][0];
            d1[nt][1] = __expf(d1[nt][1] - m0); s0e += d1[nt][1];
            d1[nt][2] = __expf(d1[nt][2] - m1); s1e += d1[nt][2];
            d1[nt][3] = __expf(d1[nt][3] - m1); s1e += d1[nt][3];
        }
        s0e += __shfl_xor_sync(0xffffffffu, s0e, 1);
        s0e += __shfl_xor_sync(0xffffffffu, s0e, 2);
        s1e += __shfl_xor_sync(0xffffffffu, s1e, 1);
        s1e += __shfl_xor_sync(0xffffffffu, s1e, 2);

        float2* exc = (float2*)(smb + OFF_EXC);
        if ((l & 3) == 0) {
            exc[half * 128 + sr0]     = make_float2(m0, s0e);
            exc[half * 128 + sr0 + 8] = make_float2(m1, s1e);
        }
        __syncthreads();

        {
            float2 a0 = exc[sr0],        b0 = exc[128 + sr0];
            float2 a1 = exc[sr0 + 8],    b1 = exc[128 + sr0 + 8];
            float M0 = fmaxf(a0.x, b0.x);
            float D0 = a0.y * __expf(a0.x - M0) + b0.y * __expf(b0.x - M0);
            float M1 = fmaxf(a1.x, b1.x);
            float D1v = a1.y * __expf(a1.x - M1) + b1.y * __expf(b1.x - M1);
            float sc0 = __expf(m0 - M0) / D0;
            float sc1 = __expf(m1 - M1) / D1v;

            // P store [k][s] bf16 + exact fp32 mass
            #pragma unroll
            for (int nt = 0; nt < 4; nt++) {
                #pragma unroll
                for (int bb = 0; bb < 2; bb++) {
                    const int k = n0 + nt * 8 + (l & 3) * 2 + bb;
                    float p0 = d1[nt][bb]     * sc0;
                    float p1 = d1[nt][2 + bb] * sc1;
                    asum_loc[nt * 2 + bb] += p0 + p1;
                    *(__nv_bfloat16*)(smb + OFF_PH + k * PSTR + 2 * sr0) =
                        __float2bfloat16_rn(p0);
                    *(__nv_bfloat16*)(smb + OFF_PH + k * PSTR + 2 * (sr0 + 8)) =
                        __float2bfloat16_rn(p1);
                }
            }
        }
        __syncthreads();   // P complete

        // ---- phase 4: GEMM2  D2[c][k] += X P^T  (full chunk, 16 warps) ----
        #pragma unroll
        for (int sq = 0; sq < 8; sq++) {
            uint32_t Ah[4];
            ldsm4(Ah, sb + OFF_XH + (t0 + raN) * XSTR + sq * 32 + caN);
            #pragma unroll
            for (int ntp = 0; ntp < 2; ntp++) {
                uint32_t Bh[4];
                ldsm4(Bh, sb + OFF_PH + (n0 + ntp * 16 + rbX) * PSTR + sq * 32 + cb16);
                mma16816(vacc[2*ntp],   Ah, Bh);
                mma16816(vacc[2*ntp+1], Ah, Bh + 2);
            }
        }
        __syncthreads();   // X/P free for next chunk
    }

    // ---- asum reduction: over s within warp (shfl), across warps via smem ----
    {
        float* asred = (float*)(smb + OFF_ASR);
        #pragma unroll
        for (int i = 0; i < 8; i++) {
            float v = asum_loc[i];
            v += __shfl_xor_sync(0xffffffffu, v, 4);
            v += __shfl_xor_sync(0xffffffffu, v, 8);
            v += __shfl_xor_sync(0xffffffffu, v, 16);
            asum_loc[i] = v;
        }
        if ((l & 3) == l) {   // lanes 0..3
            #pragma unroll
            for (int nt = 0; nt < 4; nt++)
                #pragma unroll
                for (int bb = 0; bb < 2; bb++)
                    asred[w * 32 + nt * 8 + l * 2 + bb] = asum_loc[nt * 2 + bb];
        }
    }

    // ---- vacc -> vbuf [k][130] (reuse X region) ----
    float* vbuf = (float*)smb;
    #pragma unroll
    for (int nt = 0; nt < 4; nt++)
        #pragma unroll
        for (int i = 0; i < 4; i++) {
            int cc = t0 + (l >> 2) + (i >> 1) * 8;
            int kk = n0 + nt * 8 + (l & 3) * 2 + (i & 1);
            vbuf[kk * 130 + cc] = vacc[nt][i];
        }
    __syncthreads();

    if (tid < K_CL) {
        const float* asred = (const float*)(smb + OFF_ASR);
        const int hh = tid >> 5, kl = tid & 31;
        float a = 0.f;
        #pragma unroll
        for (int j = 0; j < 8; j++) a += asred[(2 * j + hh) * 32 + kl];
        g_apart[(n * SPLIT + sp) * K_CL + tid] = a;
    }

    float* vp = g_vpart + (size_t)(n * SPLIT + sp) * K_CL * C_DIM;
    #pragma unroll
    for (int r = 0; r < 16; r++) {
        int idx = tid + THREADS * r;
        vp[idx] = vbuf[(idx >> 7) * 130 + (idx & 127)];
    }
}

// ---- reduce partials, subtract a*cent, intra-normalize, partial global sums ----
__global__ void __launch_bounds__(256)
netvlad_reduce(const float* __restrict__ cent, float* __restrict__ out) {
    __shared__ float red[8];
    const int n   = blockIdx.y;
    const int kg  = blockIdx.x;
    const int tid = threadIdx.x;
    const int w   = tid >> 5, l = tid & 31;
    const int k   = kg * 8 + w;

    float as = 0.f;
    #pragma unroll
    for (int p = 0; p < SPLIT; p++) as += g_apart[(n * SPLIT + p) * K_CL + k];

    float4 v = make_float4(0.f, 0.f, 0.f, 0.f);
    #pragma unroll
    for (int p = 0; p < SPLIT; p++) {
        const float4* vp = (const float4*)(g_vpart +
            (size_t)(n * SPLIT + p) * K_CL * C_DIM + k * C_DIM);
        float4 t = vp[l];
        v.x += t.x; v.y += t.y; v.z += t.z; v.w += t.w;
    }
    float4 ct = ((const float4*)(cent + k * C_DIM))[l];
    v.x -= as * ct.x; v.y -= as * ct.y; v.z -= as * ct.z; v.w -= as * ct.w;

    float ss = v.x * v.x + v.y * v.y + v.z * v.z + v.w * v.w;
    #pragma unroll
    for (int o = 16; o; o >>= 1) ss += __shfl_xor_sync(0xffffffffu, ss, o);
    float inv = 1.f / fmaxf(sqrtf(ss), EPSV);
    v.x *= inv; v.y *= inv; v.z *= inv; v.w *= inv;
    ((float4*)(out + (size_t)n * K_CL * C_DIM + k * C_DIM))[l] = v;

    if (l == 0) red[w] = ss * inv * inv;
    __syncthreads();
    if (tid == 0) {
        float g = 0.f;
        #pragma unroll
        for (int i = 0; i < 8; i++) g += red[i];
        g_gsum[n * 8 + kg] = g;
    }
}

__global__ void __launch_bounds__(256)
netvlad_scale(float* __restrict__ out) {
    const int n   = blockIdx.x;
    const int tid = threadIdx.x;
    float g = 0.f;
    #pragma unroll
    for (int i = 0; i < 8; i++) g += g_gsum[n * 8 + i];
    const float ginv = 1.f / fmaxf(sqrtf(g), EPSV);

    float4* ob = (float4*)(out + (size_t)n * K_CL * C_DIM);
    #pragma unroll
    for (int r = 0; r < 8; r++) {
        float4 v = ob[tid + 256 * r];
        v.x *= ginv; v.y *= ginv; v.z *= ginv; v.w *= ginv;
        ob[tid + 256 * r] = v;
    }
}

extern "C" void kernel_launch(void* const* d_in, const int* in_sizes, int n_in,
                              void* d_out, int out_size) {
    const float* x     = (const float*)d_in[0];
    const float* convw = (const float*)d_in[1];
    const float* cent  = (const float*)d_in[2];
    float*       out   = (float*)d_out;

    cudaFuncSetAttribute(netvlad_main,
                         cudaFuncAttributeMaxDynamicSharedMemorySize, SMEM_BYTES);
    netvlad_main<<<dim3(SPLIT, N_IMG), THREADS, SMEM_BYTES>>>(x, convw);
    netvlad_reduce<<<dim3(8, N_IMG), 256>>>(cent, out);
    netvlad_scale<<<N_IMG, 256>>>(out);
}

// round 17
// speedup vs baseline: 1.4826x; 1.4826x over previous
#include <cuda_runtime.h>
#include <cuda_bf16.h>
#include <cstdint>
#include <math.h>

#define N_IMG   32
#define C_DIM   128
#define K_CL    64
#define S_TOT   12544
#define SC      128
#define NCHUNK  98
#define SPLIT   9
#define CPB     11
#define THREADS 512
#define EPSV    1e-12f

#define XSTR    272         // X row stride bytes (256+16)
#define WSTR    272
#define PSTR    272
#define LSW     68          // Ls row stride words

// smem byte offsets
#define OFF_XH0 0
#define OFF_XH1 (OFF_XH0 + 128 * XSTR)      //  34816
#define OFF_WH  (OFF_XH1 + 128 * XSTR)      //  69632
#define OFF_LS0 (OFF_WH  +  64 * WSTR)      //  87040
#define OFF_LS1 (OFF_LS0 + 128 * LSW * 4)   // 121856
#define OFF_PH  (OFF_LS1 + 128 * LSW * 4)   // 156672
#define OFF_ASR (OFF_PH  +  64 * PSTR)      // 174080
#define SMEM_BYTES (OFF_ASR + 8 * 64 * 4)   // 176128

// named barriers
#define BID_LSFULL 1    // +b
#define BID_LSFREE 3    // +b
#define BID_XFREE  5    // +b
#define BID_G1LOC  7
#define BID_G2LOC  8
#define BID_G2DONE 9
#define BID_JOIN   10   // block-wide join before vbuf reuse of X region

__device__ float g_vpart[(size_t)N_IMG * SPLIT * K_CL * C_DIM];
__device__ float g_apart[N_IMG * SPLIT * K_CL];
__device__ float g_gsum[N_IMG * 8];

// ---------------- PTX helpers ----------------
__device__ __forceinline__ void bar_sync(int id, int cnt) {
    asm volatile("bar.sync %0, %1;" :: "r"(id), "r"(cnt) : "memory");
}
__device__ __forceinline__ void bar_arrive(int id, int cnt) {
    asm volatile("bar.arrive %0, %1;" :: "r"(id), "r"(cnt) : "memory");
}
__device__ __forceinline__ void ldsm4(uint32_t* r, uint32_t a) {
    asm volatile("ldmatrix.sync.aligned.m8n8.x4.shared.b16 {%0,%1,%2,%3}, [%4];"
        : "=r"(r[0]), "=r"(r[1]), "=r"(r[2]), "=r"(r[3]) : "r"(a));
}
__device__ __forceinline__ void ldsm4t(uint32_t* r, uint32_t a) {
    asm volatile("ldmatrix.sync.aligned.m8n8.x4.trans.shared.b16 {%0,%1,%2,%3}, [%4];"
        : "=r"(r[0]), "=r"(r[1]), "=r"(r[2]), "=r"(r[3]) : "r"(a));
}
__device__ __forceinline__ void mma16816(float* d, const uint32_t* a, const uint32_t* b) {
    asm volatile("mma.sync.aligned.m16n8k16.row.col.f32.bf16.bf16.f32 "
        "{%0,%1,%2,%3}, {%4,%5,%6,%7}, {%8,%9}, {%0,%1,%2,%3};"
        : "+f"(d[0]), "+f"(d[1]), "+f"(d[2]), "+f"(d[3])
        : "r"(a[0]), "r"(a[1]), "r"(a[2]), "r"(a[3]), "r"(b[0]), "r"(b[1]));
}
__device__ __forceinline__ uint32_t pack_hi(float a, float b) {
    __nv_bfloat16 ah = __float2bfloat16_rn(a);
    __nv_bfloat16 bh = __float2bfloat16_rn(b);
    return (uint32_t)__bfloat16_as_ushort(ah) | ((uint32_t)__bfloat16_as_ushort(bh) << 16);
}
__device__ __forceinline__ void conv_store32(char* dst, const float4* ld) {
    #pragma unroll
    for (int g4 = 0; g4 < 4; g4++) {
        float f[8] = { ld[2*g4].x, ld[2*g4].y, ld[2*g4].z, ld[2*g4].w,
                       ld[2*g4+1].x, ld[2*g4+1].y, ld[2*g4+1].z, ld[2*g4+1].w };
        uint32_t hh[4];
        #pragma unroll
        for (int j = 0; j < 4; j++) hh[j] = pack_hi(f[2*j], f[2*j+1]);
        *(uint4*)(dst + 16 * g4) = make_uint4(hh[0], hh[1], hh[2], hh[3]);
    }
}

__global__ void __launch_bounds__(THREADS, 1)
netvlad_main(const float* __restrict__ x, const float* __restrict__ convw) {
    extern __shared__ char smb[];
    const uint32_t sb = (uint32_t)__cvta_generic_to_shared(smb);

    const int n   = blockIdx.y;
    const int sp  = blockIdx.x;
    const int tid = threadIdx.x;
    const int w   = tid >> 5, l = tid & 31;

    // ---- W -> bf16 hi tile [k][WSTR] ----
    {
        const int k = tid >> 3, cs = (tid & 7) * 16;
        const float* wg = convw + k * C_DIM + cs;
        #pragma unroll
        for (int g = 0; g < 2; g++) {
            uint32_t hh[4];
            #pragma unroll
            for (int j = 0; j < 4; j++)
                hh[j] = pack_hi(wg[8 * g + 2 * j], wg[8 * g + 2 * j + 1]);
            *(uint4*)(smb + OFF_WH + k * WSTR + (cs + 8 * g) * 2) =
                make_uint4(hh[0], hh[1], hh[2], hh[3]);
        }
    }
    __syncthreads();

    const int chunk0 = sp * CPB;
    const int nch    = min(NCHUNK, chunk0 + CPB) - chunk0;
    const int sbase  = chunk0 * SC;
    const float* xb  = x + (size_t)n * C_DIM * S_TOT;

    const uint32_t XHOF[2] = { OFF_XH0, OFF_XH1 };
    const uint32_t LSOF[2] = { OFF_LS0, OFF_LS1 };

    const uint32_t rbX  = ((l >> 4) & 1) * 8 + (l & 7);
    const uint32_t cb16 = ((l >> 3) & 1) * 16;

    if (w < 8) {
        // ========== G1: stage X half0 + GEMM1 (full chunk, all 64 k) ==========
        const int s0 = w * 16;
        const uint32_t raT = ((l >> 4) & 1) * 8 + (l & 7);
        const uint32_t caT = (s0 + ((l >> 3) & 1) * 8) * 2;
        const int Lc  = tid >> 1;
        const int px0 = (tid & 1) * 32;
        const uint32_t xo = Lc * XSTR + px0 * 2;

        float4 ld[8];
        {
            const float* g = xb + (size_t)Lc * S_TOT + sbase + px0;
            #pragma unroll
            for (int r = 0; r < 8; r++) ld[r] = *(const float4*)(g + 4 * r);
        }

        for (int j = 0; j < nch; j++) {
            const int b = j & 1;
            bar_sync(BID_XFREE + b, 512);
            conv_store32(smb + XHOF[b] + xo, ld);
            bar_sync(BID_G1LOC, 256);

            if (j + 1 < nch) {
                const float* g = xb + (size_t)Lc * S_TOT + sbase + (j + 1) * SC + px0;
                #pragma unroll
                for (int r = 0; r < 8; r++) ld[r] = *(const float4*)(g + 4 * r);
            }

            float d1[8][4];
            #pragma unroll
            for (int t = 0; t < 8; t++)
                #pragma unroll
                for (int i = 0; i < 4; i++) d1[t][i] = 0.f;

            #pragma unroll
            for (int kq = 0; kq < 8; kq++) {
                uint32_t Ah[4];
                ldsm4t(Ah, sb + XHOF[b] + (kq * 16 + raT) * XSTR + caT);
                #pragma unroll
                for (int ntp = 0; ntp < 4; ntp++) {
                    uint32_t Bh[4];
                    ldsm4(Bh, sb + OFF_WH + (ntp * 16 + rbX) * WSTR + kq * 32 + cb16);
                    mma16816(d1[2*ntp],   Ah, Bh);
                    mma16816(d1[2*ntp+1], Ah, Bh + 2);
                }
            }

            if (j >= 2) bar_sync(BID_LSFREE + b, 512);
            {
                char* Lsb = smb + LSOF[b];
                const int sr = s0 + (l >> 2);
                const int kk = (l & 3) * 2;
                #pragma unroll
                for (int tt = 0; tt < 8; tt++) {
                    *(float2*)(Lsb + ((sr    ) * LSW + tt * 8 + kk) * 4) =
                        make_float2(d1[tt][0], d1[tt][1]);
                    *(float2*)(Lsb + ((sr + 8) * LSW + tt * 8 + kk) * 4) =
                        make_float2(d1[tt][2], d1[tt][3]);
                }
            }
            bar_arrive(BID_LSFULL + b, 512);
        }
        bar_sync(BID_JOIN, 512);   // wait for all GEMM2 to finish
    } else {
        // ========== G2: stage X half1 + softmax + GEMM2 + asum ==========
        const int t2 = tid - 256;
        const int wi = w - 8;
        const int c0 = wi * 16;
        const uint32_t raN = ((l >> 3) & 1) * 8 + (l & 7);
        const uint32_t caN = ((l >> 4) & 1) * 16;
        const int q   = t2 & 3;
        const int Lc2 = t2 >> 1;
        const int px1 = 64 + (t2 & 1) * 32;
        const uint32_t xo2 = Lc2 * XSTR + px1 * 2;

        float vacc[8][4];
        #pragma unroll
        for (int t = 0; t < 8; t++)
            #pragma unroll
            for (int i = 0; i < 4; i++) vacc[t][i] = 0.f;
        float asum_loc[16];
        #pragma unroll
        for (int i = 0; i < 16; i++) asum_loc[i] = 0.f;

        float4 ld2[8];
        #pragma unroll
        for (int pj = 0; pj < 2; pj++) {
            const float* g = xb + (size_t)Lc2 * S_TOT + sbase + pj * SC + px1;
            #pragma unroll
            for (int r = 0; r < 8; r++) ld2[r] = *(const float4*)(g + 4 * r);
            conv_store32(smb + XHOF[pj] + xo2, ld2);
            bar_arrive(BID_XFREE + pj, 512);
        }

        for (int j = 0; j < nch; j++) {
            const int b = j & 1;
            if (j + 2 < nch) {
                const float* g = xb + (size_t)Lc2 * S_TOT + sbase + (j + 2) * SC + px1;
                #pragma unroll
                for (int r = 0; r < 8; r++) ld2[r] = *(const float4*)(g + 4 * r);
            }
            bar_sync(BID_LSFULL + b, 512);

            const float* Lsb = (const float*)(smb + LSOF[b]);
            #pragma unroll
            for (int hp = 0; hp < 2; hp++) {
                const int p = hp * 64 + (t2 >> 2);
                const float* row = Lsb + p * LSW + q;
                float lg[16];
                #pragma unroll
                for (int jx = 0; jx < 16; jx++) lg[jx] = row[4 * jx];

                float m = lg[0];
                #pragma unroll
                for (int jx = 1; jx < 16; jx++) m = fmaxf(m, lg[jx]);
                m = fmaxf(m, __shfl_xor_sync(0xffffffffu, m, 1));
                m = fmaxf(m, __shfl_xor_sync(0xffffffffu, m, 2));
                float ssum = 0.f;
                #pragma unroll
                for (int jx = 0; jx < 16; jx++) { lg[jx] = __expf(lg[jx] - m); ssum += lg[jx]; }
                ssum += __shfl_xor_sync(0xffffffffu, ssum, 1);
                ssum += __shfl_xor_sync(0xffffffffu, ssum, 2);
                const float inv = 1.f / ssum;

                #pragma unroll
                for (int jx = 0; jx < 16; jx++) {
                    float pv = lg[jx] * inv;
                    asum_loc[jx] += pv;
                    *(__nv_bfloat16*)(smb + OFF_PH + (q + 4 * jx) * PSTR + 2 * p) =
                        __float2bfloat16_rn(pv);
                }
            }
            bar_arrive(BID_LSFREE + b, 512);
            bar_sync(BID_G2LOC, 256);

            #pragma unroll
            for (int sq = 0; sq < 8; sq++) {
                uint32_t Ah[4];
                ldsm4(Ah, sb + XHOF[b] + (c0 + raN) * XSTR + sq * 32 + caN);
                #pragma unroll
                for (int ntp = 0; ntp < 4; ntp++) {
                    uint32_t Bh[4];
                    ldsm4(Bh, sb + OFF_PH + (ntp * 16 + rbX) * PSTR + sq * 32 + cb16);
                    mma16816(vacc[2*ntp],   Ah, Bh);
                    mma16816(vacc[2*ntp+1], Ah, Bh + 2);
                }
            }
            bar_sync(BID_G2DONE, 256);

            if (j + 2 < nch) {
                conv_store32(smb + XHOF[b] + xo2, ld2);
                bar_arrive(BID_XFREE + b, 512);
            }
        }

        // asum publish
        {
            float* asred = (float*)(smb + OFF_ASR);
            #pragma unroll
            for (int jx = 0; jx < 16; jx++) {
                float v = asum_loc[jx];
                v += __shfl_xor_sync(0xffffffffu, v, 4);
                v += __shfl_xor_sync(0xffffffffu, v, 8);
                v += __shfl_xor_sync(0xffffffffu, v, 16);
                if (l < 4) asred[wi * 64 + l + 4 * jx] = v;
            }
        }
        bar_sync(BID_JOIN, 512);   // all warps past GEMM2; X region dead

        // vacc -> vbuf [k][130] (reuse X region)
        float* vbuf = (float*)smb;
        #pragma unroll
        for (int tt = 0; tt < 8; tt++)
            #pragma unroll
            for (int i = 0; i < 4; i++) {
                const int cc = c0 + (l >> 2) + ((i >> 1) ? 8 : 0);
                const int kk = tt * 8 + (l & 3) * 2 + (i & 1);
                vbuf[kk * 130 + cc] = vacc[tt][i];
            }
    }
    __syncthreads();   // vbuf + asred complete

    if (tid < K_CL) {
        const float* asred = (const float*)(smb + OFF_ASR);
        float a = 0.f;
        #pragma unroll
        for (int i = 0; i < 8; i++) a += asred[i * 64 + tid];
        g_apart[(n * SPLIT + sp) * K_CL + tid] = a;
    }

    float* vp = g_vpart + (size_t)(n * SPLIT + sp) * K_CL * C_DIM;
    const float* vbuf = (const float*)smb;
    #pragma unroll
    for (int r = 0; r < 16; r++) {
        int idx = tid + THREADS * r;
        vp[idx] = vbuf[(idx >> 7) * 130 + (idx & 127)];
    }
}

// ---- reduce partials, subtract a*cent, intra-normalize, partial global sums ----
__global__ void __launch_bounds__(256)
netvlad_reduce(const float* __restrict__ cent, float* __restrict__ out) {
    __shared__ float red[8];
    const int n   = blockIdx.y;
    const int kg  = blockIdx.x;
    const int tid = threadIdx.x;
    const int w   = tid >> 5, l = tid & 31;
    const int k   = kg * 8 + w;

    float as = 0.f;
    #pragma unroll
    for (int p = 0; p < SPLIT; p++) as += g_apart[(n * SPLIT + p) * K_CL + k];

    float4 v = make_float4(0.f, 0.f, 0.f, 0.f);
    #pragma unroll
    for (int p = 0; p < SPLIT; p++) {
        const float4* vp = (const float4*)(g_vpart +
            (size_t)(n * SPLIT + p) * K_CL * C_DIM + k * C_DIM);
        float4 t = vp[l];
        v.x += t.x; v.y += t.y; v.z += t.z; v.w += t.w;
    }
    float4 ct = ((const float4*)(cent + k * C_DIM))[l];
    v.x -= as * ct.x; v.y -= as * ct.y; v.z -= as * ct.z; v.w -= as * ct.w;

    float ss = v.x * v.x + v.y * v.y + v.z * v.z + v.w * v.w;
    #pragma unroll
    for (int o = 16; o; o >>= 1) ss += __shfl_xor_sync(0xffffffffu, ss, o);
    float inv = 1.f / fmaxf(sqrtf(ss), EPSV);
    v.x *= inv; v.y *= inv; v.z *= inv; v.w *= inv;
    ((float4*)(out + (size_t)n * K_CL * C_DIM + k * C_DIM))[l] = v;

    if (l == 0) red[w] = ss * inv * inv;
    __syncthreads();
    if (tid == 0) {
        float g = 0.f;
        #pragma unroll
        for (int i = 0; i < 8; i++) g += red[i];
        g_gsum[n * 8 + kg] = g;
    }
}

__global__ void __launch_bounds__(256)
netvlad_scale(float* __restrict__ out) {
    const int n   = blockIdx.x;
    const int tid = threadIdx.x;
    float g = 0.f;
    #pragma unroll
    for (int i = 0; i < 8; i++) g += g_gsum[n * 8 + i];
    const float ginv = 1.f / fmaxf(sqrtf(g), EPSV);

    float4* ob = (float4*)(out + (size_t)n * K_CL * C_DIM);
    #pragma unroll
    for (int r = 0; r < 8; r++) {
        float4 v = ob[tid + 256 * r];
        v.x *= ginv; v.y *= ginv; v.z *= ginv; v.w *= ginv;
        ob[tid + 256 * r] = v;
    }
}

extern "C" void kernel_launch(void* const* d_in, const int* in_sizes, int n_in,
                              void* d_out, int out_size) {
    const float* x     = (const float*)d_in[0];
    const float* convw = (const float*)d_in[1];
    const float* cent  = (const float*)d_in[2];
    float*       out   = (float*)d_out;

    cudaFuncSetAttribute(netvlad_main,
                         cudaFuncAttributeMaxDynamicSharedMemorySize, SMEM_BYTES);
    netvlad_main<<<dim3(SPLIT, N_IMG), THREADS, SMEM_BYTES>>>(x, convw);
    netvlad_reduce<<<dim3(8, N_IMG), 256>>>(cent, out);
    netvlad_scale<<<N_IMG, 256>>>(out);
}